// round 9
// baseline (speedup 1.0000x reference)
#include <cuda_runtime.h>
#include <cuda_bf16.h>
#include <cstdint>

#define DEV_INLINE __device__ __forceinline__

constexpr int Bb = 8;
constexpr int Nn = 4096;

// ---------------- static device scratch (no allocation) ----------------
__device__ float    g_h32[Bb * Nn * 64];          // h fp32 (8 MB)
__device__ unsigned g_hpk_hi[Bb * (Nn/2) * 64];   // h bf16, node-pair packed (4 MB)

// ============================================================================
// Kernel 1: h[b,n,j] = sum_{m,a} x[b,n,m,a]*W[m,p(j),a,w(j)]
// 128 threads: thread = (4-node group, p). W-LDS amortized over 4 nodes;
// x loads prefetched one ka4-iteration ahead; pair packing thread-local.
// ============================================================================
__global__ void __launch_bounds__(128)
spconv_h_kernel(const float* __restrict__ x, const float* __restrict__ wgt)
{
    __shared__ float ws[128 * 64];   // ws[ka*64 + j],  j = p*16 + w
    const int t = threadIdx.x;
    const int b = blockIdx.y;
    const int ng = t >> 2;                    // 0..31
    const int p  = t & 3;
    const int node0 = blockIdx.x * 128 + ng * 4;

    for (int idx = t; idx < 128 * 64; idx += 128) {
        int ka = idx >> 6, j = idx & 63;
        int m = ka >> 5, a = ka & 31, pp = j >> 4, w = j & 15;
        ws[idx] = wgt[(((m * 4 + pp) * 32 + a) << 4) + w];
    }
    __syncthreads();

    float acc[4][16];
#pragma unroll
    for (int nd = 0; nd < 4; nd++)
#pragma unroll
        for (int i = 0; i < 16; i++) acc[nd][i] = 0.f;

    const float* xr = x + (size_t)(b * Nn + node0) * 128;
    float4 nxt[4];
#pragma unroll
    for (int nd = 0; nd < 4; nd++) nxt[nd] = *(const float4*)(xr + nd * 128);

#pragma unroll 1
    for (int ka4 = 0; ka4 < 32; ka4++) {
        float4 cur[4];
#pragma unroll
        for (int nd = 0; nd < 4; nd++) cur[nd] = nxt[nd];
        if (ka4 < 31) {
#pragma unroll
            for (int nd = 0; nd < 4; nd++)
                nxt[nd] = *(const float4*)(xr + nd * 128 + (ka4 + 1) * 4);
        }
        float xa[4][4];
#pragma unroll
        for (int nd = 0; nd < 4; nd++) {
            xa[nd][0]=cur[nd].x; xa[nd][1]=cur[nd].y;
            xa[nd][2]=cur[nd].z; xa[nd][3]=cur[nd].w;
        }
#pragma unroll
        for (int i = 0; i < 4; i++) {
            const float4* wr = (const float4*)&ws[(ka4 * 4 + i) * 64 + p * 16];
            float4 w0 = wr[0], w1 = wr[1], w2 = wr[2], w3 = wr[3];
#pragma unroll
            for (int nd = 0; nd < 4; nd++) {
                const float xs = xa[nd][i];
                acc[nd][ 0]=fmaf(xs,w0.x,acc[nd][ 0]); acc[nd][ 1]=fmaf(xs,w0.y,acc[nd][ 1]);
                acc[nd][ 2]=fmaf(xs,w0.z,acc[nd][ 2]); acc[nd][ 3]=fmaf(xs,w0.w,acc[nd][ 3]);
                acc[nd][ 4]=fmaf(xs,w1.x,acc[nd][ 4]); acc[nd][ 5]=fmaf(xs,w1.y,acc[nd][ 5]);
                acc[nd][ 6]=fmaf(xs,w1.z,acc[nd][ 6]); acc[nd][ 7]=fmaf(xs,w1.w,acc[nd][ 7]);
                acc[nd][ 8]=fmaf(xs,w2.x,acc[nd][ 8]); acc[nd][ 9]=fmaf(xs,w2.y,acc[nd][ 9]);
                acc[nd][10]=fmaf(xs,w2.z,acc[nd][10]); acc[nd][11]=fmaf(xs,w2.w,acc[nd][11]);
                acc[nd][12]=fmaf(xs,w3.x,acc[nd][12]); acc[nd][13]=fmaf(xs,w3.y,acc[nd][13]);
                acc[nd][14]=fmaf(xs,w3.z,acc[nd][14]); acc[nd][15]=fmaf(xs,w3.w,acc[nd][15]);
            }
        }
    }

    // fp32 h for epilogue
#pragma unroll
    for (int nd = 0; nd < 4; nd++) {
        float* hp = g_h32 + (size_t)(b * Nn + node0 + nd) * 64 + p * 16;
#pragma unroll
        for (int w4 = 0; w4 < 4; w4++)
            *(float4*)(hp + w4 * 4) = make_float4(acc[nd][w4*4+0], acc[nd][w4*4+1],
                                                  acc[nd][w4*4+2], acc[nd][w4*4+3]);
    }

    // node-pair packed bf16: g_hpk_hi[b][pair][j]
#pragma unroll
    for (int pr = 0; pr < 2; pr++) {
        const size_t pb = ((size_t)(b * 2048 + (node0 >> 1) + pr)) * 64 + p * 16;
        unsigned hi[16];
#pragma unroll
        for (int w = 0; w < 16; w++) {
            __nv_bfloat162 t2 = __floats2bfloat162_rn(acc[pr*2+0][w], acc[pr*2+1][w]);
            hi[w] = *reinterpret_cast<unsigned*>(&t2);
        }
#pragma unroll
        for (int w4 = 0; w4 < 4; w4++)
            *(uint4*)(g_hpk_hi + pb + w4 * 4) =
                make_uint4(hi[w4*4], hi[w4*4+1], hi[w4*4+2], hi[w4*4+3]);
    }
}

// ============================================================================
// Kernel 2: per-batch C = adj @ h, fused rowsum/normalize/self-loop/relu/bias.
// BM=64 BN=64 BK=128 (512B/row/visit for DRAM row-buffer locality), 512 thr,
// warp grid 4x4 (warp tile 16x16), double-buffered smem, one barrier/tile.
// ============================================================================
constexpr int A_STR   = 68;                    // u32 per A row (64 kpairs + 4 pad)
constexpr int B_STR   = 72;                    // u32 per B kpair row (64 + 8 pad)
constexpr int A_STAGE = 64 * A_STR;            // 4352
constexpr int B_STAGE = 64 * B_STR;            // 4608
constexpr int OFF_A  = 0;                      // 2 stages
constexpr int OFF_B  = 2 * A_STAGE;            // 8704
constexpr int OFF_RS = OFF_B + 2 * B_STAGE;    // 17920 (64*9 floats)
constexpr int OFF_RI = OFF_RS + 576;           // 18496 (64 floats)
constexpr int SMEM_U32 = OFF_RI + 64;          // 18560
constexpr int SMEM_BYTES = SMEM_U32 * 4;       // 74240

DEV_INLINE void mma_bf16(float* c, const unsigned* a, const unsigned* b) {
    asm volatile(
        "mma.sync.aligned.m16n8k16.row.col.f32.bf16.bf16.f32 "
        "{%0,%1,%2,%3}, {%4,%5,%6,%7}, {%8,%9}, {%0,%1,%2,%3};\n"
        : "+f"(c[0]), "+f"(c[1]), "+f"(c[2]), "+f"(c[3])
        : "r"(a[0]), "r"(a[1]), "r"(a[2]), "r"(a[3]), "r"(b[0]), "r"(b[1]));
}

DEV_INLINE void ldsm4(unsigned* r, uint32_t addr) {
    asm volatile(
        "ldmatrix.sync.aligned.m8n8.x4.shared.b16 {%0,%1,%2,%3}, [%4];\n"
        : "=r"(r[0]), "=r"(r[1]), "=r"(r[2]), "=r"(r[3]) : "r"(addr));
}

__global__ void __launch_bounds__(512, 2)
spconv_gemm_kernel(const float* __restrict__ adj, const float* __restrict__ bias,
                   float* __restrict__ out)
{
    extern __shared__ unsigned sm[];
    const uint32_t smb = (uint32_t)__cvta_generic_to_shared(sm);

    const int t    = threadIdx.x;
    const int lane = t & 31, warp = t >> 5;
    const int g = lane >> 2, tg = lane & 3;
    const int wrow = warp >> 2, wcol = warp & 3;     // 4 x 4 warp grid
    const int bx = blockIdx.x, b = blockIdx.y;

    const int lm_row = lane & 15;
    const int lm_kp  = ((lane >> 4) & 1) * 4;

    // A: thread row t>>3 (8 thr/row), 64B chunk t&7 (16 floats) — coalesced
    const int arow = t >> 3, achk = t & 7;
    const float* adj_base =
        adj + ((size_t)(b * Nn) + (size_t)bx * 64 + arow) * Nn + achk * 16;
    // B: kpair t>>3, 8 u32 cols (t&7)*8
    const int bkp = t >> 3, bn8 = (t & 7) * 8;
    const unsigned* hpH = g_hpk_hi + (size_t)b * 131072 + bkp * 64 + bn8;

    float acc[2][4];
#pragma unroll
    for (int nf = 0; nf < 2; nf++)
#pragma unroll
        for (int i = 0; i < 4; i++) acc[nf][i] = 0.f;

    float rsum = 0.f;
    float4 va[4];
    uint4  vb0, vb1;

    auto ldg = [&](int kt) {
#pragma unroll
        for (int i = 0; i < 4; i++)
            va[i] = *(const float4*)(adj_base + kt * 128 + i * 4);
        vb0 = *(const uint4*)(hpH + (size_t)kt * 4096);
        vb1 = *(const uint4*)(hpH + (size_t)kt * 4096 + 4);
    };
    auto sts = [&](int s) {
        unsigned u[8];
#pragma unroll
        for (int i = 0; i < 4; i++) {
            rsum += (va[i].x + va[i].y) + (va[i].z + va[i].w);
            __nv_bfloat162 p0 = __floats2bfloat162_rn(va[i].x, va[i].y);
            __nv_bfloat162 p1 = __floats2bfloat162_rn(va[i].z, va[i].w);
            u[2*i]   = *reinterpret_cast<unsigned*>(&p0);
            u[2*i+1] = *reinterpret_cast<unsigned*>(&p1);
        }
        unsigned* As = sm + OFF_A + s * A_STAGE + arow * A_STR + achk * 8;
        *(uint4*)(As)     = make_uint4(u[0], u[1], u[2], u[3]);
        *(uint4*)(As + 4) = make_uint4(u[4], u[5], u[6], u[7]);
        unsigned* Bs = sm + OFF_B + s * B_STAGE + bkp * B_STR + bn8;
        *(uint4*)(Bs)     = vb0;
        *(uint4*)(Bs + 4) = vb1;
    };
    auto compute = [&](int s) {
        const unsigned* Bh = sm + OFF_B + s * B_STAGE;
        const uint32_t ahb = smb + (OFF_A + s * A_STAGE) * 4;
#pragma unroll
        for (int ks = 0; ks < 8; ks++) {
            unsigned bh[2][2];
#pragma unroll
            for (int nf = 0; nf < 2; nf++) {
                int n = wcol * 16 + nf * 8 + g;
                int k0 = (ks * 8 + tg) * B_STR + n;
                bh[nf][0] = Bh[k0];  bh[nf][1] = Bh[k0 + 4 * B_STR];
            }
            unsigned ah[4];
            int aoff = ((wrow * 16 + lm_row) * A_STR + ks * 8 + lm_kp) * 4;
            ldsm4(ah, ahb + aoff);
#pragma unroll
            for (int nf = 0; nf < 2; nf++)
                mma_bf16(acc[nf], ah, bh[nf]);
        }
    };

    // ---- pipeline: double buffer, one barrier per k-tile ----
    ldg(0);
    sts(0);
    __syncthreads();
#pragma unroll 1
    for (int kt = 0; kt < 32; kt++) {
        const int cur = kt & 1;
        if (kt < 31) ldg(kt + 1);
        compute(cur);
        if (kt < 31) {
            sts(1 - cur);
            __syncthreads();
        }
    }
    __syncthreads();

    // ---- rowsum reduce ----
    float* rs   = (float*)(sm + OFF_RS);   // [64][9]
    float* rinv = (float*)(sm + OFF_RI);   // [64]
    rs[arow * 9 + achk] = rsum;
    __syncthreads();
    if (t < 64) {
        float s_ = 1.0f;   // self loop
#pragma unroll
        for (int q = 0; q < 8; q++) s_ += rs[t * 9 + q];
        rinv[t] = 1.0f / s_;
    }
    __syncthreads();

    // ---- epilogue: out = relu((S + h)*rinv) + bias ----
    const int r0 = wrow * 16 + g;
#pragma unroll
    for (int nf = 0; nf < 2; nf++) {
        int c  = wcol * 16 + nf * 8 + 2 * tg;
        float ri0 = rinv[r0], ri1 = rinv[r0 + 8];
        int gr0 = bx * 64 + r0;
        size_t o0 = ((size_t)(b * Nn + gr0)) * 64 + c;
        size_t o1 = o0 + (size_t)8 * 64;
        float2 h0 = *(const float2*)(g_h32 + o0);
        float2 h1 = *(const float2*)(g_h32 + o1);
        float bz0 = __ldg(bias + c), bz1 = __ldg(bias + c + 1);
        float2 w0, w1;
        w0.x = fmaxf((acc[nf][0] + h0.x) * ri0, 0.f) + bz0;
        w0.y = fmaxf((acc[nf][1] + h0.y) * ri0, 0.f) + bz1;
        w1.x = fmaxf((acc[nf][2] + h1.x) * ri1, 0.f) + bz0;
        w1.y = fmaxf((acc[nf][3] + h1.y) * ri1, 0.f) + bz1;
        *(float2*)(out + o0) = w0;
        *(float2*)(out + o1) = w1;
    }
}

// ============================================================================
extern "C" void kernel_launch(void* const* d_in, const int* in_sizes, int n_in,
                              void* d_out, int out_size)
{
    const float* x    = (const float*)d_in[0];
    const float* adj  = (const float*)d_in[1];
    const float* wgt  = (const float*)d_in[2];
    const float* bias = (const float*)d_in[3];
    float* out = (float*)d_out;

    cudaFuncSetAttribute(spconv_gemm_kernel,
                         cudaFuncAttributeMaxDynamicSharedMemorySize, SMEM_BYTES);

    spconv_h_kernel<<<dim3(32, 8), 128>>>(x, wgt);
    spconv_gemm_kernel<<<dim3(64, 8), 512, SMEM_BYTES>>>(adj, bias, out);
}